// round 2
// baseline (speedup 1.0000x reference)
#include <cuda_runtime.h>
#include <math.h>

#define B_ 2
#define S_ 4096
#define C_ 1280
#define H_ 8
#define D_ 160
#define M_ (B_*S_)          // 8192 tokens total

#define FPAD 164            // padded row stride for Q/K/V tiles in smem (floats)
#define SPAD 65             // padded row stride for score tile

// Scratch: Q, K, V, attention-output (all [M_, C_] fp32). Static device globals
// per the no-allocation rule. ~168 MB total.
__device__ float g_q [(size_t)M_ * C_];
__device__ float g_k [(size_t)M_ * C_];
__device__ float g_v [(size_t)M_ * C_];
__device__ float g_ao[(size_t)M_ * C_];

// ---------------------------------------------------------------------------
// SGEMM: C[M,N] = A[M,K] @ B[K,N] (+bias), 128x128 block, 8x8 per thread.
// ---------------------------------------------------------------------------
__global__ __launch_bounds__(256) void sgemm128(
    const float* __restrict__ A, const float* __restrict__ Bm,
    float* __restrict__ C, const float* __restrict__ bias,
    int M, int N, int K)
{
    __shared__ float As[8][128];   // A tile, transposed: As[k][row]
    __shared__ float Bs[8][128];   // B tile: Bs[k][col]

    const int tid = threadIdx.x;
    const int row0 = blockIdx.y * 128;
    const int col0 = blockIdx.x * 128;

    const int ar = tid >> 1, ac = (tid & 1) * 4;     // A load: 128 rows x 8 cols
    const int br = tid >> 5, bc = (tid & 31) * 4;    // B load: 8 rows x 128 cols
    const int tx = tid & 15, ty = tid >> 4;          // 16x16 thread grid

    float acc[8][8];
    #pragma unroll
    for (int i = 0; i < 8; i++)
        #pragma unroll
        for (int j = 0; j < 8; j++) acc[i][j] = 0.f;

    const float* Ap = A  + (size_t)(row0 + ar) * K + ac;
    const float* Bp = Bm + (size_t)br * N + col0 + bc;

    for (int k0 = 0; k0 < K; k0 += 8) {
        float4 av = *(const float4*)(Ap + k0);
        float4 bv = *(const float4*)(Bp + (size_t)k0 * N);
        __syncthreads();
        As[ac + 0][ar] = av.x;
        As[ac + 1][ar] = av.y;
        As[ac + 2][ar] = av.z;
        As[ac + 3][ar] = av.w;
        *(float4*)&Bs[br][bc] = bv;
        __syncthreads();

        #pragma unroll
        for (int kk = 0; kk < 8; kk++) {
            float4 a0 = *(const float4*)&As[kk][ty * 8];
            float4 a1 = *(const float4*)&As[kk][ty * 8 + 4];
            float4 b0 = *(const float4*)&Bs[kk][tx * 4];        // cols tx*4..+3
            float4 b1 = *(const float4*)&Bs[kk][64 + tx * 4];   // cols 64+tx*4..+3
            float a[8] = {a0.x, a0.y, a0.z, a0.w, a1.x, a1.y, a1.z, a1.w};
            float b[8] = {b0.x, b0.y, b0.z, b0.w, b1.x, b1.y, b1.z, b1.w};
            #pragma unroll
            for (int i = 0; i < 8; i++)
                #pragma unroll
                for (int j = 0; j < 8; j++)
                    acc[i][j] += a[i] * b[j];
        }
    }

    float4 bb0 = {0.f, 0.f, 0.f, 0.f}, bb1 = {0.f, 0.f, 0.f, 0.f};
    if (bias) {
        bb0 = *(const float4*)(bias + col0 + tx * 4);
        bb1 = *(const float4*)(bias + col0 + 64 + tx * 4);
    }
    #pragma unroll
    for (int i = 0; i < 8; i++) {
        size_t roff = (size_t)(row0 + ty * 8 + i) * N + col0;
        float4 r0 = {acc[i][0] + bb0.x, acc[i][1] + bb0.y,
                     acc[i][2] + bb0.z, acc[i][3] + bb0.w};
        float4 r1 = {acc[i][4] + bb1.x, acc[i][5] + bb1.y,
                     acc[i][6] + bb1.z, acc[i][7] + bb1.w};
        *(float4*)(C + roff + tx * 4)      = r0;
        *(float4*)(C + roff + 64 + tx * 4) = r1;
    }
}

// ---------------------------------------------------------------------------
// Flash attention, fp32. Grid: (S/64, H, B). 256 threads.
// Thread (ty,tx) owns S-subtile rows ty*4..+3, cols {tx+16j}; O cols tx*10..+9.
// ---------------------------------------------------------------------------
__global__ __launch_bounds__(256) void flash_kernel(
    const float* __restrict__ q, const float* __restrict__ k,
    const float* __restrict__ v, float* __restrict__ o)
{
    extern __shared__ float sm[];
    float* sQ  = sm;                    // 64*FPAD
    float* sK  = sQ + 64 * FPAD;        // 64*FPAD
    float* sV  = sK + 64 * FPAD;        // 64*FPAD
    float* sP  = sV + 64 * FPAD;        // 64*SPAD
    float* sM  = sP + 64 * SPAD;        // 64
    float* sL  = sM + 64;               // 64
    float* sAl = sL + 64;               // 64

    const int tid = threadIdx.x;
    const int qt = blockIdx.x, h = blockIdx.y, b = blockIdx.z;
    const int tx = tid & 15, ty = tid >> 4;
    const float scale = 0.07905694150420949f;  // 1/sqrt(160)

    // Load Q tile (64 x 160) -> padded smem
    const float* qbase = q + (size_t)(b * S_ + qt * 64) * C_ + h * D_;
    #pragma unroll
    for (int t = 0; t < 10; t++) {
        int e = tid + t * 256;
        int r = e / 40, c = e % 40;
        *(float4*)(sQ + r * FPAD + c * 4) =
            *(const float4*)(qbase + (size_t)r * C_ + c * 4);
    }
    if (tid < 64) { sM[tid] = -INFINITY; sL[tid] = 0.f; }

    float acc[4][10];
    #pragma unroll
    for (int i = 0; i < 4; i++)
        #pragma unroll
        for (int c = 0; c < 10; c++) acc[i][c] = 0.f;

    const float* kbase0 = k + (size_t)b * S_ * C_ + h * D_;
    const float* vbase0 = v + (size_t)b * S_ * C_ + h * D_;

    for (int jt = 0; jt < S_ / 64; jt++) {
        __syncthreads();   // previous iteration's sK/sV/sP readers are done
        const float* kb = kbase0 + (size_t)jt * 64 * C_;
        const float* vb = vbase0 + (size_t)jt * 64 * C_;
        #pragma unroll
        for (int t = 0; t < 10; t++) {
            int e = tid + t * 256;
            int r = e / 40, c = e % 40;
            *(float4*)(sK + r * FPAD + c * 4) =
                *(const float4*)(kb + (size_t)r * C_ + c * 4);
            *(float4*)(sV + r * FPAD + c * 4) =
                *(const float4*)(vb + (size_t)r * C_ + c * 4);
        }
        __syncthreads();

        // S = Q K^T for this 64x64 tile
        float sc[4][4];
        #pragma unroll
        for (int i = 0; i < 4; i++)
            #pragma unroll
            for (int j = 0; j < 4; j++) sc[i][j] = 0.f;

        #pragma unroll 2
        for (int d4 = 0; d4 < 40; d4++) {
            float4 qv[4], kv[4];
            #pragma unroll
            for (int i = 0; i < 4; i++)
                qv[i] = *(const float4*)(sQ + (ty * 4 + i) * FPAD + d4 * 4);
            #pragma unroll
            for (int j = 0; j < 4; j++)
                kv[j] = *(const float4*)(sK + (tx + 16 * j) * FPAD + d4 * 4);
            #pragma unroll
            for (int i = 0; i < 4; i++)
                #pragma unroll
                for (int j = 0; j < 4; j++)
                    sc[i][j] += qv[i].x * kv[j].x + qv[i].y * kv[j].y +
                                qv[i].z * kv[j].z + qv[i].w * kv[j].w;
        }
        #pragma unroll
        for (int i = 0; i < 4; i++)
            #pragma unroll
            for (int j = 0; j < 4; j++)
                sP[(ty * 4 + i) * SPAD + tx + 16 * j] = sc[i][j] * scale;
        __syncthreads();

        // Online softmax: one thread per row
        if (tid < 64) {
            const int r = tid;
            float mold = sM[r], mrow = mold;
            float* pr = sP + r * SPAD;
            #pragma unroll 8
            for (int j = 0; j < 64; j++) mrow = fmaxf(mrow, pr[j]);
            float sum = 0.f;
            #pragma unroll 8
            for (int j = 0; j < 64; j++) {
                float p = __expf(pr[j] - mrow);
                pr[j] = p;
                sum += p;
            }
            float alpha = __expf(mold - mrow);   // exp(-inf)=0 on first tile
            sM[r] = mrow;
            sL[r] = sL[r] * alpha + sum;
            sAl[r] = alpha;
        }
        __syncthreads();

        // Rescale accumulators, then O += P @ V
        float al[4];
        #pragma unroll
        for (int i = 0; i < 4; i++) al[i] = sAl[ty * 4 + i];
        #pragma unroll
        for (int i = 0; i < 4; i++)
            #pragma unroll
            for (int c = 0; c < 10; c++) acc[i][c] *= al[i];

        #pragma unroll 4
        for (int j = 0; j < 64; j++) {
            float p[4];
            #pragma unroll
            for (int i = 0; i < 4; i++) p[i] = sP[(ty * 4 + i) * SPAD + j];
            const float* vr = sV + j * FPAD + tx * 10;
            #pragma unroll
            for (int c = 0; c < 10; c++) {
                float vv = vr[c];
                #pragma unroll
                for (int i = 0; i < 4; i++) acc[i][c] += p[i] * vv;
            }
        }
    }

    // Epilogue: normalize and store
    float* obase = o + (size_t)(b * S_ + qt * 64) * C_ + h * D_;
    float linv[4];
    #pragma unroll
    for (int i = 0; i < 4; i++) linv[i] = 1.f / sL[ty * 4 + i];
    #pragma unroll
    for (int i = 0; i < 4; i++) {
        float* orow = obase + (size_t)(ty * 4 + i) * C_ + tx * 10;
        #pragma unroll
        for (int c = 0; c < 10; c++) orow[c] = acc[i][c] * linv[i];
    }
}

// ---------------------------------------------------------------------------
extern "C" void kernel_launch(void* const* d_in, const int* in_sizes, int n_in,
                              void* d_out, int out_size)
{
    const float* hs = (const float*)d_in[0];
    const float* wq = (const float*)d_in[1];
    const float* wk = (const float*)d_in[2];
    const float* wv = (const float*)d_in[3];
    const float* wo = (const float*)d_in[4];
    const float* bo = (const float*)d_in[5];
    float* out = (float*)d_out;

    float *pq, *pk, *pv, *pao;
    cudaGetSymbolAddress((void**)&pq,  g_q);
    cudaGetSymbolAddress((void**)&pk,  g_k);
    cudaGetSymbolAddress((void**)&pv,  g_v);
    cudaGetSymbolAddress((void**)&pao, g_ao);

    dim3 gg(C_ / 128, M_ / 128);
    sgemm128<<<gg, 256>>>(hs, wq, pq, nullptr, M_, C_, C_);
    sgemm128<<<gg, 256>>>(hs, wk, pk, nullptr, M_, C_, C_);
    sgemm128<<<gg, 256>>>(hs, wv, pv, nullptr, M_, C_, C_);

    const int FSM = (3 * 64 * FPAD + 64 * SPAD + 3 * 64) * (int)sizeof(float);
    cudaFuncSetAttribute(flash_kernel,
                         cudaFuncAttributeMaxDynamicSharedMemorySize, FSM);
    flash_kernel<<<dim3(S_ / 64, H_, B_), 256, FSM>>>(pq, pk, pv, pao);

    sgemm128<<<gg, 256>>>(pao, wo, out, bo, M_, C_, C_);
}

// round 5
// speedup vs baseline: 3.0130x; 3.0130x over previous
#include <cuda_runtime.h>
#include <cuda_bf16.h>
#include <math.h>
#include <stdint.h>

#define B_ 2
#define S_ 4096
#define C_ 1280
#define H_ 8
#define D_ 160
#define M_ (B_*S_)          // 8192 tokens

// ---------------------------------------------------------------------------
// Global scratch (bf16 hi/lo everywhere; no fp32 intermediates)
// ---------------------------------------------------------------------------
__device__ __nv_bfloat16 g_hAh[(size_t)M_*C_], g_hAl[(size_t)M_*C_];
__device__ __nv_bfloat16 g_qh [(size_t)M_*C_], g_ql [(size_t)M_*C_];
__device__ __nv_bfloat16 g_kh [(size_t)M_*C_], g_kl [(size_t)M_*C_];
__device__ __nv_bfloat16 g_vh [(size_t)M_*C_], g_vl [(size_t)M_*C_];
__device__ __nv_bfloat16 g_aoh[(size_t)M_*C_], g_aol[(size_t)M_*C_];
__device__ __nv_bfloat16 g_wqh[(size_t)C_*C_], g_wql[(size_t)C_*C_];
__device__ __nv_bfloat16 g_wkh[(size_t)C_*C_], g_wkl[(size_t)C_*C_];
__device__ __nv_bfloat16 g_wvh[(size_t)C_*C_], g_wvl[(size_t)C_*C_];
__device__ __nv_bfloat16 g_woh[(size_t)C_*C_], g_wol[(size_t)C_*C_];

// ---------------------------------------------------------------------------
// PTX helpers (all valid on compute_103: ldmatrix / mma.sync / cp.async)
// ---------------------------------------------------------------------------
__device__ __forceinline__ uint32_t smem_u32(const void* p) {
    uint32_t a;
    asm("{ .reg .u64 t; cvta.to.shared.u64 t, %1; cvt.u32.u64 %0, t; }"
        : "=r"(a) : "l"(p));
    return a;
}
__device__ __forceinline__ void ldsm4(uint32_t* r, uint32_t a) {
    asm volatile("ldmatrix.sync.aligned.m8n8.x4.shared.b16 {%0,%1,%2,%3}, [%4];"
        : "=r"(r[0]), "=r"(r[1]), "=r"(r[2]), "=r"(r[3]) : "r"(a));
}
__device__ __forceinline__ void ldsm4t(uint32_t* r, uint32_t a) {
    asm volatile("ldmatrix.sync.aligned.m8n8.x4.trans.shared.b16 {%0,%1,%2,%3}, [%4];"
        : "=r"(r[0]), "=r"(r[1]), "=r"(r[2]), "=r"(r[3]) : "r"(a));
}
__device__ __forceinline__ void mma16816(float* c, const uint32_t* a,
                                         uint32_t b0, uint32_t b1) {
    asm volatile(
        "mma.sync.aligned.m16n8k16.row.col.f32.bf16.bf16.f32 "
        "{%0,%1,%2,%3}, {%4,%5,%6,%7}, {%8,%9}, {%0,%1,%2,%3};"
        : "+f"(c[0]), "+f"(c[1]), "+f"(c[2]), "+f"(c[3])
        : "r"(a[0]), "r"(a[1]), "r"(a[2]), "r"(a[3]), "r"(b0), "r"(b1));
}
__device__ __forceinline__ void cpa16(uint32_t dst, const void* src) {
    asm volatile("cp.async.cg.shared.global [%0], [%1], 16;"
        :: "r"(dst), "l"(src));
}
#define CP_COMMIT() asm volatile("cp.async.commit_group;" ::: "memory")
#define CP_WAIT1()  asm volatile("cp.async.wait_group 1;" ::: "memory")

__device__ __forceinline__ uint32_t pack_bf16(float lo, float hi) {
    __nv_bfloat162 t = __floats2bfloat162_rn(lo, hi);
    return *(uint32_t*)&t;
}
__device__ __forceinline__ void split_pair(float a, float b,
                                           uint32_t& hreg, uint32_t& lreg) {
    __nv_bfloat162 hh = __floats2bfloat162_rn(a, b);
    float ra = a - __bfloat162float(hh.x);
    float rb = b - __bfloat162float(hh.y);
    hreg = *(uint32_t*)&hh;
    lreg = pack_bf16(ra, rb);
}
__device__ __forceinline__ void split_store(__nv_bfloat16* H, __nv_bfloat16* L,
                                            size_t off, float a, float b) {
    __nv_bfloat162 hh = __floats2bfloat162_rn(a, b);
    float ra = a - __bfloat162float(hh.x);
    float rb = b - __bfloat162float(hh.y);
    *(__nv_bfloat162*)(H + off) = hh;
    *(__nv_bfloat162*)(L + off) = __floats2bfloat162_rn(ra, rb);
}

// ---------------------------------------------------------------------------
// conversions
// ---------------------------------------------------------------------------
__global__ void split_kernel(const float* __restrict__ in,
                             __nv_bfloat16* __restrict__ hi,
                             __nv_bfloat16* __restrict__ lo, size_t n)
{
    size_t i = (size_t)blockIdx.x * blockDim.x + threadIdx.x;
    if (i >= n) return;
    float x = in[i];
    __nv_bfloat16 h = __float2bfloat16(x);
    hi[i] = h;
    lo[i] = __float2bfloat16(x - __bfloat162float(h));
}

__global__ __launch_bounds__(256) void transpose_split_kernel(
    const float* __restrict__ W,
    __nv_bfloat16* __restrict__ Bh, __nv_bfloat16* __restrict__ Bl,
    int K, int N)
{
    __shared__ float t[32][33];
    const int tx = threadIdx.x, ty = threadIdx.y;
    const int n0 = blockIdx.x * 32, k0 = blockIdx.y * 32;
    #pragma unroll
    for (int i = 0; i < 4; i++)
        t[ty + i * 8][tx] = W[(size_t)(k0 + ty + i * 8) * N + n0 + tx];
    __syncthreads();
    #pragma unroll
    for (int i = 0; i < 4; i++) {
        float x = t[tx][ty + i * 8];            // = W[k0+tx][n0+ty+i*8]
        __nv_bfloat16 h = __float2bfloat16(x);
        size_t o = (size_t)(n0 + ty + i * 8) * K + k0 + tx;
        Bh[o] = h;
        Bl[o] = __float2bfloat16(x - __bfloat162float(h));
    }
}

// ---------------------------------------------------------------------------
// Split-bf16 GEMM via mma.sync: C[M,N] = A[M,K] @ Wt[N,K]^T (+bias)(*scale)
// 128x128 CTA tile, 8 warps (2m x 4n), K-chunk 32, 2-stage cp.async pipeline.
// ---------------------------------------------------------------------------
#define GROWB   80                        // smem row stride bytes (40 bf16)
#define GA_BYTES (128*GROWB)              // one array tile = 10240 B
#define GSTAGE  (4*GA_BYTES)              // Ah, Al, Bh, Bl
#define GSMEM   (2*GSTAGE)                // 81920 B

__global__ __launch_bounds__(256, 2) void gemm_mma(
    const __nv_bfloat16* __restrict__ Ah, const __nv_bfloat16* __restrict__ Al,
    const __nv_bfloat16* __restrict__ Bh, const __nv_bfloat16* __restrict__ Bl,
    float* __restrict__ Cf, const float* __restrict__ bias,
    __nv_bfloat16* __restrict__ Ch, __nv_bfloat16* __restrict__ Cl,
    float scale, int Mm, int Nn, int Kk)
{
    extern __shared__ char smem[];
    const uint32_t sb = smem_u32(smem);
    const int tid = threadIdx.x, lane = tid & 31, wid = tid >> 5;
    const int wm = wid >> 2, wn = wid & 3;
    const int g = lane >> 2, q = lane & 3;
    const int m0 = blockIdx.y * 128, n0 = blockIdx.x * 128;

    const __nv_bfloat16* gsrc[4] = {
        Ah + (size_t)m0 * Kk, Al + (size_t)m0 * Kk,
        Bh + (size_t)n0 * Kk, Bl + (size_t)n0 * Kk };
    const int larr = tid & 3;
    const __nv_bfloat16* lsrc = gsrc[larr];

    // loader: 512 16B-chunks per array / 64 thread-groups -> 8 per thread
    auto load_chunk = [&](int c, int st) {
        uint32_t sdst = sb + st * GSTAGE + larr * GA_BYTES;
        int k0 = c * 32;
        #pragma unroll
        for (int i = 0; i < 8; i++) {
            int e = (tid >> 2) + i * 64;      // 0..511
            int row = e >> 2, cg = e & 3;
            cpa16(sdst + row * GROWB + cg * 16,
                  lsrc + (size_t)row * Kk + k0 + cg * 8);
        }
    };

    float acc[4][4][4];
    #pragma unroll
    for (int a = 0; a < 4; a++)
        #pragma unroll
        for (int b = 0; b < 4; b++)
            #pragma unroll
            for (int d = 0; d < 4; d++) acc[a][b][d] = 0.f;

    load_chunk(0, 0); CP_COMMIT();
    load_chunk(1, 1); CP_COMMIT();

    const int NC = Kk / 32;
    const int arow = wm * 64 + (lane & 15);
    const int acolh = (lane >> 4) << 3;
    const int jj = lane >> 3, rin = lane & 7;

    for (int c = 0; c < NC; c++) {
        int st = c & 1;
        CP_WAIT1();
        __syncthreads();
        uint32_t sAh = sb + st * GSTAGE;
        uint32_t sAl = sAh + GA_BYTES;
        uint32_t sBh = sAh + 2 * GA_BYTES;
        uint32_t sBl = sAh + 3 * GA_BYTES;

        #pragma unroll
        for (int ks = 0; ks < 2; ks++) {
            uint32_t aH[4][4], aL[4][4];
            int acol = ks * 16 + acolh;
            #pragma unroll
            for (int mt = 0; mt < 4; mt++) {
                uint32_t ro = (arow + mt * 16) * GROWB + acol * 2;
                ldsm4(aH[mt], sAh + ro);
                ldsm4(aL[mt], sAl + ro);
            }
            #pragma unroll
            for (int nt2 = 0; nt2 < 2; nt2++) {
                int brow = wn * 32 + nt2 * 16 + ((jj >> 1) << 3) + rin;
                int bcol = ks * 16 + ((jj & 1) << 3);
                uint32_t bh[4], bl[4];
                uint32_t bo = brow * GROWB + bcol * 2;
                ldsm4(bh, sBh + bo);
                ldsm4(bl, sBl + bo);
                #pragma unroll
                for (int mt = 0; mt < 4; mt++)
                    #pragma unroll
                    for (int hf = 0; hf < 2; hf++) {
                        float* cc = acc[mt][nt2 * 2 + hf];
                        mma16816(cc, aH[mt], bh[hf*2], bh[hf*2+1]);
                        mma16816(cc, aH[mt], bl[hf*2], bl[hf*2+1]);
                        mma16816(cc, aL[mt], bh[hf*2], bh[hf*2+1]);
                    }
            }
        }
        __syncthreads();
        if (c + 2 < NC) load_chunk(c + 2, st);
        CP_COMMIT();
    }

    // epilogue
    #pragma unroll
    for (int mt = 0; mt < 4; mt++)
        #pragma unroll
        for (int nt = 0; nt < 4; nt++) {
            int r   = m0 + wm * 64 + mt * 16 + g;
            int col = n0 + wn * 32 + nt * 8 + 2 * q;
            float v0 = acc[mt][nt][0] * scale, v1 = acc[mt][nt][1] * scale;
            float v2 = acc[mt][nt][2] * scale, v3 = acc[mt][nt][3] * scale;
            if (bias) {
                float2 bb = *(const float2*)(bias + col);
                v0 += bb.x; v1 += bb.y; v2 += bb.x; v3 += bb.y;
            }
            if (Cf) {
                *(float2*)(Cf + (size_t)r * Nn + col)       = make_float2(v0, v1);
                *(float2*)(Cf + (size_t)(r + 8) * Nn + col) = make_float2(v2, v3);
            }
            if (Ch) {
                split_store(Ch, Cl, (size_t)r * Nn + col, v0, v1);
                split_store(Ch, Cl, (size_t)(r + 8) * Nn + col, v2, v3);
            }
        }
}

// ---------------------------------------------------------------------------
// Flash attention via mma.sync (split bf16). CTA: 128 q-rows, 8 warps (m16
// each). KV tiles of 32 keys, 2-stage cp.async pipeline. Q pre-scaled.
// ---------------------------------------------------------------------------
#define DPAD_B  336                       // smem row stride bytes (168 bf16)
#define QBYTES  (128*DPAD_B)              // 43008
#define KVARR   (32*DPAD_B)               // 10752
#define KVSTAGE (4*KVARR)                 // Kh, Kl, Vh, Vl = 43008
#define FSMEM   (2*QBYTES + 2*KVSTAGE)    // 172032

__global__ __launch_bounds__(256, 1) void flash_mma(
    const __nv_bfloat16* __restrict__ qh, const __nv_bfloat16* __restrict__ ql,
    const __nv_bfloat16* __restrict__ kh, const __nv_bfloat16* __restrict__ kl,
    const __nv_bfloat16* __restrict__ vh, const __nv_bfloat16* __restrict__ vl,
    __nv_bfloat16* __restrict__ oh, __nv_bfloat16* __restrict__ ol)
{
    extern __shared__ char smem[];
    const uint32_t sb = smem_u32(smem);
    const int tid = threadIdx.x, lane = tid & 31, wid = tid >> 5;
    const int g = lane >> 2, q = lane & 3;
    const int qt = blockIdx.x, h = blockIdx.y, b = blockIdx.z;
    const size_t rowbase = (size_t)b * S_ + qt * 128;
    const int hcol = h * D_;

    // --- Q tile load (128 x 160 hi/lo) via cp.async ---
    {
        const __nv_bfloat16* src = (tid & 1) ? ql : qh;
        uint32_t dst = sb + (tid & 1) * QBYTES;
        #pragma unroll
        for (int i = 0; i < 20; i++) {
            int e = (tid >> 1) + i * 128;     // 0..2559
            int row = e / 20, cg = e % 20;
            cpa16(dst + row * DPAD_B + cg * 16,
                  src + (rowbase + row) * C_ + hcol + cg * 8);
        }
    }
    const __nv_bfloat16* kvsrc4[4] = { kh, kl, vh, vl };
    const int karr = tid & 3;
    const __nv_bfloat16* ksrc = kvsrc4[karr];
    auto load_kv = [&](int t, int st) {
        uint32_t dst = sb + 2 * QBYTES + st * KVSTAGE + karr * KVARR;
        size_t krow0 = (size_t)b * S_ + t * 32;
        #pragma unroll
        for (int i = 0; i < 10; i++) {
            int e = (tid >> 2) + i * 64;      // 0..639
            int row = e / 20, cg = e % 20;
            cpa16(dst + row * DPAD_B + cg * 16,
                  ksrc + (krow0 + row) * C_ + hcol + cg * 8);
        }
    };
    load_kv(0, 0); CP_COMMIT();               // group: Q + KV tile 0
    load_kv(1, 1); CP_COMMIT();

    float o[20][4];
    #pragma unroll
    for (int d = 0; d < 20; d++)
        #pragma unroll
        for (int i = 0; i < 4; i++) o[d][i] = 0.f;
    float m0r = -INFINITY, m1r = -INFINITY, l0r = 0.f, l1r = 0.f;

    const uint32_t sQh = sb, sQl = sb + QBYTES;
    const int arow = wid * 16 + (lane & 15);
    const int acolh = (lane >> 4) << 3;
    const int jj = lane >> 3, rin = lane & 7;

    for (int t = 0; t < S_ / 32; t++) {
        int st = t & 1;
        CP_WAIT1();
        __syncthreads();
        uint32_t sKh = sb + 2 * QBYTES + st * KVSTAGE;
        uint32_t sKl = sKh + KVARR, sVh = sKh + 2 * KVARR, sVl = sKh + 3 * KVARR;

        // ---- S = Q K^T (m16 x n32, k=160), 3-term split ----
        float sacc[4][4];
        #pragma unroll
        for (int nt = 0; nt < 4; nt++)
            #pragma unroll
            for (int i = 0; i < 4; i++) sacc[nt][i] = 0.f;

        #pragma unroll
        for (int ks = 0; ks < 10; ks++) {
            uint32_t aH[4], aL[4];
            uint32_t ro = arow * DPAD_B + (ks * 16 + acolh) * 2;
            ldsm4(aH, sQh + ro);
            ldsm4(aL, sQl + ro);
            #pragma unroll
            for (int nt2 = 0; nt2 < 2; nt2++) {
                int brow = nt2 * 16 + ((jj >> 1) << 3) + rin;
                int bcol = ks * 16 + ((jj & 1) << 3);
                uint32_t bh[4], bl[4];
                uint32_t bo = brow * DPAD_B + bcol * 2;
                ldsm4(bh, sKh + bo);
                ldsm4(bl, sKl + bo);
                #pragma unroll
                for (int hf = 0; hf < 2; hf++) {
                    float* cc = sacc[nt2 * 2 + hf];
                    mma16816(cc, aH, bh[hf*2], bh[hf*2+1]);
                    mma16816(cc, aH, bl[hf*2], bl[hf*2+1]);
                    mma16816(cc, aL, bh[hf*2], bh[hf*2+1]);
                }
            }
        }

        // ---- online softmax (rows g and g+8, spread over the lane quad) ----
        float mx0 = -INFINITY, mx1 = -INFINITY;
        #pragma unroll
        for (int nt = 0; nt < 4; nt++) {
            mx0 = fmaxf(mx0, fmaxf(sacc[nt][0], sacc[nt][1]));
            mx1 = fmaxf(mx1, fmaxf(sacc[nt][2], sacc[nt][3]));
        }
        mx0 = fmaxf(mx0, __shfl_xor_sync(0xffffffffu, mx0, 1));
        mx0 = fmaxf(mx0, __shfl_xor_sync(0xffffffffu, mx0, 2));
        mx1 = fmaxf(mx1, __shfl_xor_sync(0xffffffffu, mx1, 1));
        mx1 = fmaxf(mx1, __shfl_xor_sync(0xffffffffu, mx1, 2));
        float mn0 = fmaxf(m0r, mx0), mn1 = fmaxf(m1r, mx1);
        float alpha0 = __expf(m0r - mn0), alpha1 = __expf(m1r - mn1);
        m0r = mn0; m1r = mn1;

        float s0 = 0.f, s1 = 0.f;
        #pragma unroll
        for (int nt = 0; nt < 4; nt++) {
            sacc[nt][0] = __expf(sacc[nt][0] - mn0); s0 += sacc[nt][0];
            sacc[nt][1] = __expf(sacc[nt][1] - mn0); s0 += sacc[nt][1];
            sacc[nt][2] = __expf(sacc[nt][2] - mn1); s1 += sacc[nt][2];
            sacc[nt][3] = __expf(sacc[nt][3] - mn1); s1 += sacc[nt][3];
        }
        s0 += __shfl_xor_sync(0xffffffffu, s0, 1);
        s0 += __shfl_xor_sync(0xffffffffu, s0, 2);
        s1 += __shfl_xor_sync(0xffffffffu, s1, 1);
        s1 += __shfl_xor_sync(0xffffffffu, s1, 2);
        l0r = l0r * alpha0 + s0;
        l1r = l1r * alpha1 + s1;

        #pragma unroll
        for (int d = 0; d < 20; d++) {
            o[d][0] *= alpha0; o[d][1] *= alpha0;
            o[d][2] *= alpha1; o[d][3] *= alpha1;
        }

        // ---- O += P V (P from sacc regs; V via ldmatrix.trans) ----
        #pragma unroll
        for (int kt = 0; kt < 2; kt++) {
            uint32_t pH[4], pL[4];
            split_pair(sacc[2*kt  ][0], sacc[2*kt  ][1], pH[0], pL[0]);
            split_pair(sacc[2*kt  ][2], sacc[2*kt  ][3], pH[1], pL[1]);
            split_pair(sacc[2*kt+1][0], sacc[2*kt+1][1], pH[2], pL[2]);
            split_pair(sacc[2*kt+1][2], sacc[2*kt+1][3], pH[3], pL[3]);
            int vk = kt * 16 + ((jj & 1) << 3) + rin;
            #pragma unroll
            for (int np = 0; np < 10; np++) {
                int vd = np * 16 + ((jj >> 1) << 3);
                uint32_t vhf[4], vlf[4];
                uint32_t vo = vk * DPAD_B + vd * 2;
                ldsm4t(vhf, sVh + vo);
                ldsm4t(vlf, sVl + vo);
                #pragma unroll
                for (int hf = 0; hf < 2; hf++) {
                    float* cc = o[np * 2 + hf];
                    mma16816(cc, pH, vhf[hf*2], vhf[hf*2+1]);
                    mma16816(cc, pH, vlf[hf*2], vlf[hf*2+1]);
                    mma16816(cc, pL, vhf[hf*2], vhf[hf*2+1]);
                }
            }
        }
        __syncthreads();
        if (t + 2 < S_ / 32) load_kv(t + 2, st);
        CP_COMMIT();
    }

    // ---- epilogue: normalize, split, store bf16 hi/lo ----
    float i0 = 1.f / l0r, i1 = 1.f / l1r;
    size_t r0 = rowbase + wid * 16 + g, r1 = r0 + 8;
    #pragma unroll
    for (int nt = 0; nt < 20; nt++) {
        int col = hcol + nt * 8 + 2 * q;
        split_store(oh, ol, r0 * C_ + col, o[nt][0] * i0, o[nt][1] * i0);
        split_store(oh, ol, r1 * C_ + col, o[nt][2] * i1, o[nt][3] * i1);
    }
}

// ---------------------------------------------------------------------------
extern "C" void kernel_launch(void* const* d_in, const int* in_sizes, int n_in,
                              void* d_out, int out_size)
{
    const float* hs = (const float*)d_in[0];
    const float* wq = (const float*)d_in[1];
    const float* wk = (const float*)d_in[2];
    const float* wv = (const float*)d_in[3];
    const float* wo = (const float*)d_in[4];
    const float* bo = (const float*)d_in[5];
    float* out = (float*)d_out;

    __nv_bfloat16 *hAh, *hAl, *qh, *ql, *kh, *kl, *vh, *vl, *aoh, *aol;
    __nv_bfloat16 *wqh, *wql, *wkh, *wkl, *wvh, *wvl, *woh, *wol;
    cudaGetSymbolAddress((void**)&hAh, g_hAh);
    cudaGetSymbolAddress((void**)&hAl, g_hAl);
    cudaGetSymbolAddress((void**)&qh,  g_qh);
    cudaGetSymbolAddress((void**)&ql,  g_ql);
    cudaGetSymbolAddress((void**)&kh,  g_kh);
    cudaGetSymbolAddress((void**)&kl,  g_kl);
    cudaGetSymbolAddress((void**)&vh,  g_vh);
    cudaGetSymbolAddress((void**)&vl,  g_vl);
    cudaGetSymbolAddress((void**)&aoh, g_aoh);
    cudaGetSymbolAddress((void**)&aol, g_aol);
    cudaGetSymbolAddress((void**)&wqh, g_wqh);
    cudaGetSymbolAddress((void**)&wql, g_wql);
    cudaGetSymbolAddress((void**)&wkh, g_wkh);
    cudaGetSymbolAddress((void**)&wkl, g_wkl);
    cudaGetSymbolAddress((void**)&wvh, g_wvh);
    cudaGetSymbolAddress((void**)&wvl, g_wvl);
    cudaGetSymbolAddress((void**)&woh, g_woh);
    cudaGetSymbolAddress((void**)&wol, g_wol);

    const size_t nA = (size_t)M_ * C_;
    split_kernel<<<(int)((nA + 255) / 256), 256>>>(hs, hAh, hAl, nA);
    dim3 tb(32, 8), tg(C_ / 32, C_ / 32);
    transpose_split_kernel<<<tg, tb>>>(wq, wqh, wql, C_, C_);
    transpose_split_kernel<<<tg, tb>>>(wk, wkh, wkl, C_, C_);
    transpose_split_kernel<<<tg, tb>>>(wv, wvh, wvl, C_, C_);
    transpose_split_kernel<<<tg, tb>>>(wo, woh, wol, C_, C_);

    cudaFuncSetAttribute(gemm_mma,
                         cudaFuncAttributeMaxDynamicSharedMemorySize, GSMEM);
    cudaFuncSetAttribute(flash_mma,
                         cudaFuncAttributeMaxDynamicSharedMemorySize, FSMEM);

    const float qscale = 0.07905694150420949f;   // 1/sqrt(160)
    dim3 gg(C_ / 128, M_ / 128);
    gemm_mma<<<gg, 256, GSMEM>>>(hAh, hAl, wqh, wql, nullptr, nullptr,
                                 qh, ql, qscale, M_, C_, C_);
    gemm_mma<<<gg, 256, GSMEM>>>(hAh, hAl, wkh, wkl, nullptr, nullptr,
                                 kh, kl, 1.f, M_, C_, C_);
    gemm_mma<<<gg, 256, GSMEM>>>(hAh, hAl, wvh, wvl, nullptr, nullptr,
                                 vh, vl, 1.f, M_, C_, C_);

    flash_mma<<<dim3(S_ / 128, H_, B_), 256, FSMEM>>>(qh, ql, kh, kl, vh, vl,
                                                      aoh, aol);

    gemm_mma<<<gg, 256, GSMEM>>>(aoh, aol, woh, wol, out, bo,
                                 nullptr, nullptr, 1.f, M_, C_, C_);
}

// round 7
// speedup vs baseline: 4.2142x; 1.3987x over previous
#include <cuda_runtime.h>
#include <cuda_bf16.h>
#include <cuda_fp16.h>
#include <math.h>
#include <stdint.h>

#define B_ 2
#define S_ 4096
#define C_ 1280
#define H_ 8
#define D_ 160
#define M_ (B_*S_)          // 8192 tokens

// ---------------------------------------------------------------------------
// Global scratch
// ---------------------------------------------------------------------------
__device__ __nv_bfloat16 g_hAh[(size_t)M_*C_], g_hAl[(size_t)M_*C_];
__device__ __half        g_hF [(size_t)M_*C_];
__device__ __nv_bfloat16 g_qh [(size_t)M_*C_], g_ql [(size_t)M_*C_];
__device__ __nv_bfloat16 g_kh [(size_t)M_*C_], g_kl [(size_t)M_*C_];
__device__ __half        g_vf [(size_t)M_*C_];
__device__ __half        g_of [(size_t)M_*C_];
__device__ __nv_bfloat16 g_wqh[(size_t)C_*C_], g_wql[(size_t)C_*C_];
__device__ __nv_bfloat16 g_wkh[(size_t)C_*C_], g_wkl[(size_t)C_*C_];
__device__ __half        g_wvf[(size_t)C_*C_];
__device__ __half        g_wof[(size_t)C_*C_];

// ---------------------------------------------------------------------------
// PTX helpers
// ---------------------------------------------------------------------------
__device__ __forceinline__ uint32_t smem_u32(const void* p) {
    uint32_t a;
    asm("{ .reg .u64 t; cvta.to.shared.u64 t, %1; cvt.u32.u64 %0, t; }"
        : "=r"(a) : "l"(p));
    return a;
}
__device__ __forceinline__ void ldsm4(uint32_t* r, uint32_t a) {
    asm volatile("ldmatrix.sync.aligned.m8n8.x4.shared.b16 {%0,%1,%2,%3}, [%4];"
        : "=r"(r[0]), "=r"(r[1]), "=r"(r[2]), "=r"(r[3]) : "r"(a));
}
__device__ __forceinline__ void ldsm4t(uint32_t* r, uint32_t a) {
    asm volatile("ldmatrix.sync.aligned.m8n8.x4.trans.shared.b16 {%0,%1,%2,%3}, [%4];"
        : "=r"(r[0]), "=r"(r[1]), "=r"(r[2]), "=r"(r[3]) : "r"(a));
}
template<bool FP16>
__device__ __forceinline__ void mma_t(float* c, const uint32_t* a,
                                      uint32_t b0, uint32_t b1) {
    if (FP16)
        asm volatile(
            "mma.sync.aligned.m16n8k16.row.col.f32.f16.f16.f32 "
            "{%0,%1,%2,%3}, {%4,%5,%6,%7}, {%8,%9}, {%0,%1,%2,%3};"
            : "+f"(c[0]), "+f"(c[1]), "+f"(c[2]), "+f"(c[3])
            : "r"(a[0]), "r"(a[1]), "r"(a[2]), "r"(a[3]), "r"(b0), "r"(b1));
    else
        asm volatile(
            "mma.sync.aligned.m16n8k16.row.col.f32.bf16.bf16.f32 "
            "{%0,%1,%2,%3}, {%4,%5,%6,%7}, {%8,%9}, {%0,%1,%2,%3};"
            : "+f"(c[0]), "+f"(c[1]), "+f"(c[2]), "+f"(c[3])
            : "r"(a[0]), "r"(a[1]), "r"(a[2]), "r"(a[3]), "r"(b0), "r"(b1));
}
__device__ __forceinline__ void cpa16(uint32_t dst, const void* src) {
    asm volatile("cp.async.cg.shared.global [%0], [%1], 16;"
        :: "r"(dst), "l"(src));
}
#define CP_COMMIT() asm volatile("cp.async.commit_group;" ::: "memory")
#define CP_WAIT1()  asm volatile("cp.async.wait_group 1;" ::: "memory")

__device__ __forceinline__ uint32_t pack_h2(float a, float b) {
    __half2 t = __floats2half2_rn(a, b);
    return *(uint32_t*)&t;
}
__device__ __forceinline__ void split_store(__nv_bfloat16* H, __nv_bfloat16* L,
                                            size_t off, float a, float b) {
    __nv_bfloat162 hh = __floats2bfloat162_rn(a, b);
    float ra = a - __bfloat162float(hh.x);
    float rb = b - __bfloat162float(hh.y);
    *(__nv_bfloat162*)(H + off) = hh;
    *(__nv_bfloat162*)(L + off) = __floats2bfloat162_rn(ra, rb);
}

// ---------------------------------------------------------------------------
// conversions
// ---------------------------------------------------------------------------
__global__ void split3_kernel(const float* __restrict__ in,
                              __nv_bfloat16* __restrict__ hi,
                              __nv_bfloat16* __restrict__ lo,
                              __half* __restrict__ hf, size_t n)
{
    size_t i = (size_t)blockIdx.x * blockDim.x + threadIdx.x;
    if (i >= n) return;
    float x = in[i];
    __nv_bfloat16 h = __float2bfloat16(x);
    hi[i] = h;
    lo[i] = __float2bfloat16(x - __bfloat162float(h));
    hf[i] = __float2half(x);
}

__global__ __launch_bounds__(256) void transpose_split_kernel(
    const float* __restrict__ W,
    __nv_bfloat16* __restrict__ Bh, __nv_bfloat16* __restrict__ Bl,
    int K, int N)
{
    __shared__ float t[32][33];
    const int tx = threadIdx.x, ty = threadIdx.y;
    const int n0 = blockIdx.x * 32, k0 = blockIdx.y * 32;
    #pragma unroll
    for (int i = 0; i < 4; i++)
        t[ty + i * 8][tx] = W[(size_t)(k0 + ty + i * 8) * N + n0 + tx];
    __syncthreads();
    #pragma unroll
    for (int i = 0; i < 4; i++) {
        float x = t[tx][ty + i * 8];
        __nv_bfloat16 h = __float2bfloat16(x);
        size_t o = (size_t)(n0 + ty + i * 8) * K + k0 + tx;
        Bh[o] = h;
        Bl[o] = __float2bfloat16(x - __bfloat162float(h));
    }
}

__global__ __launch_bounds__(256) void transpose_half_kernel(
    const float* __restrict__ W, __half* __restrict__ Bf, int K, int N)
{
    __shared__ float t[32][33];
    const int tx = threadIdx.x, ty = threadIdx.y;
    const int n0 = blockIdx.x * 32, k0 = blockIdx.y * 32;
    #pragma unroll
    for (int i = 0; i < 4; i++)
        t[ty + i * 8][tx] = W[(size_t)(k0 + ty + i * 8) * N + n0 + tx];
    __syncthreads();
    #pragma unroll
    for (int i = 0; i < 4; i++)
        Bf[(size_t)(n0 + ty + i * 8) * K + k0 + tx] = __float2half(t[tx][ty + i * 8]);
}

// ---------------------------------------------------------------------------
// Templated GEMM via mma.sync: C[M,N] = A[M,K] @ B[N,K]^T
// TERMS=3: bf16 hi/lo 3-term split. TERMS=1: fp16 single.
// EPI: 0 = bf16 hi/lo store (*scale), 1 = fp16 store, 2 = fp32 + bias store.
// 128x128 CTA tile, 8 warps (2m x 4n), K-chunk 32, 2-stage cp.async.
// ---------------------------------------------------------------------------
#define GROWB    80                       // smem row stride bytes (40 halfwords)
#define GA_BYTES (128*GROWB)              // 10240 B per array tile

template<int TERMS, bool FP16, int EPI>
__global__ __launch_bounds__(256, 2) void gemm_t(
    const uint16_t* __restrict__ Ah, const uint16_t* __restrict__ Al,
    const uint16_t* __restrict__ Bh, const uint16_t* __restrict__ Bl,
    float* __restrict__ Cf, const float* __restrict__ bias,
    uint16_t* __restrict__ Ch, uint16_t* __restrict__ Cl,
    float scale, int Nn, int Kk)
{
    constexpr int NARR = (TERMS == 3) ? 4 : 2;
    constexpr int GSTG = NARR * GA_BYTES;
    extern __shared__ char smem[];
    const uint32_t sb = smem_u32(smem);
    const int tid = threadIdx.x, lane = tid & 31, wid = tid >> 5;
    const int wm = wid >> 2, wn = wid & 3;
    const int g = lane >> 2, q = lane & 3;
    const int m0 = blockIdx.y * 128, n0 = blockIdx.x * 128;

    const uint16_t* gsrc[NARR];
    if (TERMS == 3) {
        gsrc[0] = Ah + (size_t)m0 * Kk; gsrc[1] = Al + (size_t)m0 * Kk;
        gsrc[2] = Bh + (size_t)n0 * Kk; gsrc[3] = Bl + (size_t)n0 * Kk;
    } else {
        gsrc[0] = Ah + (size_t)m0 * Kk; gsrc[1] = Bh + (size_t)n0 * Kk;
    }
    const int larr = tid & (NARR - 1);
    const int tg = tid / NARR;
    const uint16_t* lsrc = gsrc[larr];

    auto load_chunk = [&](int c, int st) {
        uint32_t sdst = sb + st * GSTG + larr * GA_BYTES;
        int k0 = c * 32;
        #pragma unroll
        for (int i = 0; i < 2 * NARR; i++) {
            int e = tg + i * (256 / NARR);   // 0..511
            int row = e >> 2, cg = e & 3;
            cpa16(sdst + row * GROWB + cg * 16,
                  lsrc + (size_t)row * Kk + k0 + cg * 8);
        }
    };

    float acc[4][4][4];
    #pragma unroll
    for (int a = 0; a < 4; a++)
        #pragma unroll
        for (int b = 0; b < 4; b++)
            #pragma unroll
            for (int d = 0; d < 4; d++) acc[a][b][d] = 0.f;

    load_chunk(0, 0); CP_COMMIT();
    load_chunk(1, 1); CP_COMMIT();

    const int NC = Kk / 32;
    const int arow = wm * 64 + (lane & 15);
    const int acolh = (lane >> 4) << 3;
    const int jj = lane >> 3, rin = lane & 7;

    for (int c = 0; c < NC; c++) {
        int st = c & 1;
        CP_WAIT1();
        __syncthreads();
        uint32_t sAh = sb + st * GSTG;
        uint32_t sAl = sAh + GA_BYTES;                       // TERMS==3 only
        uint32_t sBh = sAh + (TERMS == 3 ? 2 : 1) * GA_BYTES;
        uint32_t sBl = sAh + 3 * GA_BYTES;

        #pragma unroll
        for (int ks = 0; ks < 2; ks++) {
            uint32_t aH[4][4], aL[4][4];
            int acol = ks * 16 + acolh;
            #pragma unroll
            for (int mt = 0; mt < 4; mt++) {
                uint32_t ro = (arow + mt * 16) * GROWB + acol * 2;
                ldsm4(aH[mt], sAh + ro);
                if (TERMS == 3) ldsm4(aL[mt], sAl + ro);
            }
            #pragma unroll
            for (int nt2 = 0; nt2 < 2; nt2++) {
                int brow = wn * 32 + nt2 * 16 + ((jj >> 1) << 3) + rin;
                int bcol = ks * 16 + ((jj & 1) << 3);
                uint32_t bh[4], bl[4];
                uint32_t bo = brow * GROWB + bcol * 2;
                ldsm4(bh, sBh + bo);
                if (TERMS == 3) ldsm4(bl, sBl + bo);
                #pragma unroll
                for (int mt = 0; mt < 4; mt++)
                    #pragma unroll
                    for (int hf = 0; hf < 2; hf++) {
                        float* cc = acc[mt][nt2 * 2 + hf];
                        mma_t<FP16>(cc, aH[mt], bh[hf*2], bh[hf*2+1]);
                        if (TERMS == 3) {
                            mma_t<FP16>(cc, aH[mt], bl[hf*2], bl[hf*2+1]);
                            mma_t<FP16>(cc, aL[mt], bh[hf*2], bh[hf*2+1]);
                        }
                    }
            }
        }
        __syncthreads();
        if (c + 2 < NC) load_chunk(c + 2, st);
        CP_COMMIT();
    }

    #pragma unroll
    for (int mt = 0; mt < 4; mt++)
        #pragma unroll
        for (int nt = 0; nt < 4; nt++) {
            int r   = m0 + wm * 64 + mt * 16 + g;
            int col = n0 + wn * 32 + nt * 8 + 2 * q;
            float v0 = acc[mt][nt][0] * scale, v1 = acc[mt][nt][1] * scale;
            float v2 = acc[mt][nt][2] * scale, v3 = acc[mt][nt][3] * scale;
            if (EPI == 2) {
                float2 bb = *(const float2*)(bias + col);
                *(float2*)(Cf + (size_t)r * Nn + col) =
                    make_float2(v0 + bb.x, v1 + bb.y);
                *(float2*)(Cf + (size_t)(r + 8) * Nn + col) =
                    make_float2(v2 + bb.x, v3 + bb.y);
            } else if (EPI == 1) {
                *(__half2*)((__half*)Ch + (size_t)r * Nn + col) =
                    __floats2half2_rn(v0, v1);
                *(__half2*)((__half*)Ch + (size_t)(r + 8) * Nn + col) =
                    __floats2half2_rn(v2, v3);
            } else {
                split_store((__nv_bfloat16*)Ch, (__nv_bfloat16*)Cl,
                            (size_t)r * Nn + col, v0, v1);
                split_store((__nv_bfloat16*)Ch, (__nv_bfloat16*)Cl,
                            (size_t)(r + 8) * Nn + col, v2, v3);
            }
        }
}

// ---------------------------------------------------------------------------
// Flash attention: S = 3-term bf16 (Qh/Ql x Kh/Kl), PV = single fp16.
// CTA: 128 q-rows, 8 warps. KV tiles of 32, 2-stage cp.async.
// ---------------------------------------------------------------------------
#define DPAD_B   336                      // smem row stride bytes
#define QBYTES   (128*DPAD_B)             // 43008
#define KVARR    (32*DPAD_B)              // 10752
#define KVSTAGE3 (3*KVARR)                // Kh, Kl, Vf = 32256
#define FSMEM    (2*QBYTES + 2*KVSTAGE3)  // 150528

__global__ __launch_bounds__(256, 1) void flash_mma(
    const __nv_bfloat16* __restrict__ qh, const __nv_bfloat16* __restrict__ ql,
    const __nv_bfloat16* __restrict__ kh, const __nv_bfloat16* __restrict__ kl,
    const __half* __restrict__ vf, __half* __restrict__ of)
{
    extern __shared__ char smem[];
    const uint32_t sb = smem_u32(smem);
    const int tid = threadIdx.x, lane = tid & 31, wid = tid >> 5;
    const int g = lane >> 2, q = lane & 3;
    const int qt = blockIdx.x, h = blockIdx.y, b = blockIdx.z;
    const size_t rowbase = (size_t)b * S_ + qt * 128;
    const int hcol = h * D_;

    {   // Q tile (128 x 160 hi/lo)
        const __nv_bfloat16* src = (tid & 1) ? ql : qh;
        uint32_t dst = sb + (tid & 1) * QBYTES;
        #pragma unroll
        for (int i = 0; i < 20; i++) {
            int e = (tid >> 1) + i * 128;
            int row = e / 20, cg = e % 20;
            cpa16(dst + row * DPAD_B + cg * 16,
                  src + (rowbase + row) * C_ + hcol + cg * 8);
        }
    }
    auto load_kv = [&](int t, int st) {
        uint32_t base = sb + 2 * QBYTES + st * KVSTAGE3;
        size_t krow0 = (size_t)b * S_ + t * 32;
        const uint16_t* arr[3] = { (const uint16_t*)kh, (const uint16_t*)kl,
                                   (const uint16_t*)vf };
        #pragma unroll
        for (int a3 = 0; a3 < 3; a3++) {
            uint32_t dst = base + a3 * KVARR;
            const uint16_t* src = arr[a3];
            #pragma unroll
            for (int i = 0; i < 3; i++) {
                int e = tid + i * 256;              // need < 640
                if (e < 640) {
                    int row = e / 20, cg = e % 20;
                    cpa16(dst + row * DPAD_B + cg * 16,
                          src + (krow0 + row) * C_ + hcol + cg * 8);
                }
            }
        }
    };
    load_kv(0, 0); CP_COMMIT();            // group: Q + KV tile 0
    load_kv(1, 1); CP_COMMIT();

    float o[20][4];
    #pragma unroll
    for (int d = 0; d < 20; d++)
        #pragma unroll
        for (int i = 0; i < 4; i++) o[d][i] = 0.f;
    float m0r = -INFINITY, m1r = -INFINITY, l0r = 0.f, l1r = 0.f;

    const uint32_t sQh = sb, sQl = sb + QBYTES;
    const int arow = wid * 16 + (lane & 15);
    const int acolh = (lane >> 4) << 3;
    const int jj = lane >> 3, rin = lane & 7;

    for (int t = 0; t < S_ / 32; t++) {
        int st = t & 1;
        CP_WAIT1();
        __syncthreads();
        uint32_t sKh = sb + 2 * QBYTES + st * KVSTAGE3;
        uint32_t sKl = sKh + KVARR, sVf = sKh + 2 * KVARR;

        // ---- S = Q K^T, 3-term bf16 split ----
        float sacc[4][4];
        #pragma unroll
        for (int nt = 0; nt < 4; nt++)
            #pragma unroll
            for (int i = 0; i < 4; i++) sacc[nt][i] = 0.f;

        #pragma unroll
        for (int ks = 0; ks < 10; ks++) {
            uint32_t aH[4], aL[4];
            uint32_t ro = arow * DPAD_B + (ks * 16 + acolh) * 2;
            ldsm4(aH, sQh + ro);
            ldsm4(aL, sQl + ro);
            #pragma unroll
            for (int nt2 = 0; nt2 < 2; nt2++) {
                int brow = nt2 * 16 + ((jj >> 1) << 3) + rin;
                int bcol = ks * 16 + ((jj & 1) << 3);
                uint32_t bh[4], bl[4];
                uint32_t bo = brow * DPAD_B + bcol * 2;
                ldsm4(bh, sKh + bo);
                ldsm4(bl, sKl + bo);
                #pragma unroll
                for (int hf = 0; hf < 2; hf++) {
                    float* cc = sacc[nt2 * 2 + hf];
                    mma_t<false>(cc, aH, bh[hf*2], bh[hf*2+1]);
                    mma_t<false>(cc, aH, bl[hf*2], bl[hf*2+1]);
                    mma_t<false>(cc, aL, bh[hf*2], bh[hf*2+1]);
                }
            }
        }

        // ---- online softmax ----
        float mx0 = -INFINITY, mx1 = -INFINITY;
        #pragma unroll
        for (int nt = 0; nt < 4; nt++) {
            mx0 = fmaxf(mx0, fmaxf(sacc[nt][0], sacc[nt][1]));
            mx1 = fmaxf(mx1, fmaxf(sacc[nt][2], sacc[nt][3]));
        }
        mx0 = fmaxf(mx0, __shfl_xor_sync(0xffffffffu, mx0, 1));
        mx0 = fmaxf(mx0, __shfl_xor_sync(0xffffffffu, mx0, 2));
        mx1 = fmaxf(mx1, __shfl_xor_sync(0xffffffffu, mx1, 1));
        mx1 = fmaxf(mx1, __shfl_xor_sync(0xffffffffu, mx1, 2));
        float mn0 = fmaxf(m0r, mx0), mn1 = fmaxf(m1r, mx1);
        float alpha0 = __expf(m0r - mn0), alpha1 = __expf(m1r - mn1);
        m0r = mn0; m1r = mn1;

        float s0 = 0.f, s1 = 0.f;
        #pragma unroll
        for (int nt = 0; nt < 4; nt++) {
            sacc[nt][0] = __expf(sacc[nt][0] - mn0); s0 += sacc[nt][0];
            sacc[nt][1] = __expf(sacc[nt][1] - mn0); s0 += sacc[nt][1];
            sacc[nt][2] = __expf(sacc[nt][2] - mn1); s1 += sacc[nt][2];
            sacc[nt][3] = __expf(sacc[nt][3] - mn1); s1 += sacc[nt][3];
        }
        s0 += __shfl_xor_sync(0xffffffffu, s0, 1);
        s0 += __shfl_xor_sync(0xffffffffu, s0, 2);
        s1 += __shfl_xor_sync(0xffffffffu, s1, 1);
        s1 += __shfl_xor_sync(0xffffffffu, s1, 2);
        l0r = l0r * alpha0 + s0;
        l1r = l1r * alpha1 + s1;

        #pragma unroll
        for (int d = 0; d < 20; d++) {
            o[d][0] *= alpha0; o[d][1] *= alpha0;
            o[d][2] *= alpha1; o[d][3] *= alpha1;
        }

        // ---- O += P V, single fp16 ----
        #pragma unroll
        for (int kt = 0; kt < 2; kt++) {
            uint32_t pF[4];
            pF[0] = pack_h2(sacc[2*kt  ][0], sacc[2*kt  ][1]);
            pF[1] = pack_h2(sacc[2*kt  ][2], sacc[2*kt  ][3]);
            pF[2] = pack_h2(sacc[2*kt+1][0], sacc[2*kt+1][1]);
            pF[3] = pack_h2(sacc[2*kt+1][2], sacc[2*kt+1][3]);
            int vk = kt * 16 + ((jj & 1) << 3) + rin;
            #pragma unroll
            for (int np = 0; np < 10; np++) {
                int vd = np * 16 + ((jj >> 1) << 3);
                uint32_t vfr[4];
                ldsm4t(vfr, sVf + vk * DPAD_B + vd * 2);
                #pragma unroll
                for (int hf = 0; hf < 2; hf++)
                    mma_t<true>(o[np * 2 + hf], pF, vfr[hf*2], vfr[hf*2+1]);
            }
        }
        __syncthreads();
        if (t + 2 < S_ / 32) load_kv(t + 2, st);
        CP_COMMIT();
    }

    // ---- epilogue: normalize, store fp16 ----
    float i0 = 1.f / l0r, i1 = 1.f / l1r;
    size_t r0 = rowbase + wid * 16 + g, r1 = r0 + 8;
    #pragma unroll
    for (int nt = 0; nt < 20; nt++) {
        int col = hcol + nt * 8 + 2 * q;
        *(__half2*)(of + r0 * C_ + col) =
            __floats2half2_rn(o[nt][0] * i0, o[nt][1] * i0);
        *(__half2*)(of + r1 * C_ + col) =
            __floats2half2_rn(o[nt][2] * i1, o[nt][3] * i1);
    }
}

// ---------------------------------------------------------------------------
extern "C" void kernel_launch(void* const* d_in, const int* in_sizes, int n_in,
                              void* d_out, int out_size)
{
    const float* hs = (const float*)d_in[0];
    const float* wq = (const float*)d_in[1];
    const float* wk = (const float*)d_in[2];
    const float* wv = (const float*)d_in[3];
    const float* wo = (const float*)d_in[4];
    const float* bo = (const float*)d_in[5];
    float* out = (float*)d_out;

    __nv_bfloat16 *hAh, *hAl, *qh, *ql, *kh, *kl;
    __half *hF, *vfp, *ofp, *wvf, *wof;
    __nv_bfloat16 *wqh, *wql, *wkh, *wkl;
    cudaGetSymbolAddress((void**)&hAh, g_hAh);
    cudaGetSymbolAddress((void**)&hAl, g_hAl);
    cudaGetSymbolAddress((void**)&hF,  g_hF);
    cudaGetSymbolAddress((void**)&qh,  g_qh);
    cudaGetSymbolAddress((void**)&ql,  g_ql);
    cudaGetSymbolAddress((void**)&kh,  g_kh);
    cudaGetSymbolAddress((void**)&kl,  g_kl);
    cudaGetSymbolAddress((void**)&vfp, g_vf);
    cudaGetSymbolAddress((void**)&ofp, g_of);
    cudaGetSymbolAddress((void**)&wqh, g_wqh);
    cudaGetSymbolAddress((void**)&wql, g_wql);
    cudaGetSymbolAddress((void**)&wkh, g_wkh);
    cudaGetSymbolAddress((void**)&wkl, g_wkl);
    cudaGetSymbolAddress((void**)&wvf, g_wvf);
    cudaGetSymbolAddress((void**)&wof, g_wof);

    const size_t nA = (size_t)M_ * C_;
    split3_kernel<<<(int)((nA + 255) / 256), 256>>>(hs, hAh, hAl, hF, nA);
    dim3 tb(32, 8), tg(C_ / 32, C_ / 32);
    transpose_split_kernel<<<tg, tb>>>(wq, wqh, wql, C_, C_);
    transpose_split_kernel<<<tg, tb>>>(wk, wkh, wkl, C_, C_);
    transpose_half_kernel<<<tg, tb>>>(wv, wvf, C_, C_);
    transpose_half_kernel<<<tg, tb>>>(wo, wof, C_, C_);

    const int GS3 = 2 * 4 * GA_BYTES;     // 81920
    const int GS1 = 2 * 2 * GA_BYTES;     // 40960
    cudaFuncSetAttribute(gemm_t<3,false,0>,
                         cudaFuncAttributeMaxDynamicSharedMemorySize, GS3);
    cudaFuncSetAttribute(gemm_t<1,true,1>,
                         cudaFuncAttributeMaxDynamicSharedMemorySize, GS1);
    cudaFuncSetAttribute(gemm_t<1,true,2>,
                         cudaFuncAttributeMaxDynamicSharedMemorySize, GS1);
    cudaFuncSetAttribute(flash_mma,
                         cudaFuncAttributeMaxDynamicSharedMemorySize, FSMEM);

    const float qscale = 0.07905694150420949f;   // 1/sqrt(160)
    dim3 gg(C_ / 128, M_ / 128);
    gemm_t<3,false,0><<<gg, 256, GS3>>>(
        (const uint16_t*)hAh, (const uint16_t*)hAl,
        (const uint16_t*)wqh, (const uint16_t*)wql,
        nullptr, nullptr, (uint16_t*)qh, (uint16_t*)ql, qscale, C_, C_);
    gemm_t<3,false,0><<<gg, 256, GS3>>>(
        (const uint16_t*)hAh, (const uint16_t*)hAl,
        (const uint16_t*)wkh, (const uint16_t*)wkl,
        nullptr, nullptr, (uint16_t*)kh, (uint16_t*)kl, 1.f, C_, C_);
    gemm_t<1,true,1><<<gg, 256, GS1>>>(
        (const uint16_t*)hF, nullptr, (const uint16_t*)wvf, nullptr,
        nullptr, nullptr, (uint16_t*)vfp, nullptr, 1.f, C_, C_);

    flash_mma<<<dim3(S_ / 128, H_, B_), 256, FSMEM>>>(qh, ql, kh, kl, vfp, ofp);

    gemm_t<1,true,2><<<gg, 256, GS1>>>(
        (const uint16_t*)ofp, nullptr, (const uint16_t*)wof, nullptr,
        out, bo, nullptr, nullptr, 1.f, C_, C_);
}

// round 8
// speedup vs baseline: 7.4378x; 1.7649x over previous
#include <cuda_runtime.h>
#include <cuda_fp16.h>
#include <math.h>
#include <stdint.h>

#define B_ 2
#define S_ 4096
#define C_ 1280
#define H_ 8
#define D_ 160
#define M_ (B_*S_)          // 8192 tokens

// ---------------------------------------------------------------------------
// Global scratch (all fp16 now)
// ---------------------------------------------------------------------------
__device__ __half g_hF [(size_t)M_*C_];
__device__ __half g_qf [(size_t)M_*C_], g_kf[(size_t)M_*C_], g_vf[(size_t)M_*C_];
__device__ __half g_of [(size_t)M_*C_];
__device__ __half g_wqf[(size_t)C_*C_], g_wkf[(size_t)C_*C_];
__device__ __half g_wvf[(size_t)C_*C_], g_wof[(size_t)C_*C_];

// ---------------------------------------------------------------------------
// PTX helpers
// ---------------------------------------------------------------------------
__device__ __forceinline__ uint32_t smem_u32(const void* p) {
    uint32_t a;
    asm("{ .reg .u64 t; cvta.to.shared.u64 t, %1; cvt.u32.u64 %0, t; }"
        : "=r"(a) : "l"(p));
    return a;
}
__device__ __forceinline__ void ldsm4(uint32_t* r, uint32_t a) {
    asm volatile("ldmatrix.sync.aligned.m8n8.x4.shared.b16 {%0,%1,%2,%3}, [%4];"
        : "=r"(r[0]), "=r"(r[1]), "=r"(r[2]), "=r"(r[3]) : "r"(a));
}
__device__ __forceinline__ void ldsm4t(uint32_t* r, uint32_t a) {
    asm volatile("ldmatrix.sync.aligned.m8n8.x4.trans.shared.b16 {%0,%1,%2,%3}, [%4];"
        : "=r"(r[0]), "=r"(r[1]), "=r"(r[2]), "=r"(r[3]) : "r"(a));
}
__device__ __forceinline__ void mma_f16(float* c, const uint32_t* a,
                                        uint32_t b0, uint32_t b1) {
    asm volatile(
        "mma.sync.aligned.m16n8k16.row.col.f32.f16.f16.f32 "
        "{%0,%1,%2,%3}, {%4,%5,%6,%7}, {%8,%9}, {%0,%1,%2,%3};"
        : "+f"(c[0]), "+f"(c[1]), "+f"(c[2]), "+f"(c[3])
        : "r"(a[0]), "r"(a[1]), "r"(a[2]), "r"(a[3]), "r"(b0), "r"(b1));
}
__device__ __forceinline__ void cpa16(uint32_t dst, const void* src) {
    asm volatile("cp.async.cg.shared.global [%0], [%1], 16;"
        :: "r"(dst), "l"(src));
}
#define CP_COMMIT() asm volatile("cp.async.commit_group;" ::: "memory")
#define CP_WAIT1()  asm volatile("cp.async.wait_group 1;" ::: "memory")

__device__ __forceinline__ uint32_t pack_h2(float a, float b) {
    __half2 t = __floats2half2_rn(a, b);
    return *(uint32_t*)&t;
}

// ---------------------------------------------------------------------------
// conversions
// ---------------------------------------------------------------------------
__global__ void convert_half_kernel(const float* __restrict__ in,
                                    __half* __restrict__ out, size_t n)
{
    size_t i = (size_t)blockIdx.x * blockDim.x + threadIdx.x;
    if (i < n) out[i] = __float2half(in[i]);
}

// one launch transposes all four weight matrices (blockIdx.z selects)
__global__ __launch_bounds__(256) void transpose_half4_kernel(
    const float* __restrict__ w0, const float* __restrict__ w1,
    const float* __restrict__ w2, const float* __restrict__ w3,
    __half* __restrict__ b0, __half* __restrict__ b1,
    __half* __restrict__ b2, __half* __restrict__ b3, int K, int N)
{
    const float* W;
    __half* Bf;
    switch (blockIdx.z) {
        case 0: W = w0; Bf = b0; break;
        case 1: W = w1; Bf = b1; break;
        case 2: W = w2; Bf = b2; break;
        default: W = w3; Bf = b3; break;
    }
    __shared__ float t[32][33];
    const int tx = threadIdx.x, ty = threadIdx.y;
    const int n0 = blockIdx.x * 32, k0 = blockIdx.y * 32;
    #pragma unroll
    for (int i = 0; i < 4; i++)
        t[ty + i * 8][tx] = W[(size_t)(k0 + ty + i * 8) * N + n0 + tx];
    __syncthreads();
    #pragma unroll
    for (int i = 0; i < 4; i++)
        Bf[(size_t)(n0 + ty + i * 8) * K + k0 + tx] =
            __float2half(t[tx][ty + i * 8]);
}

// ---------------------------------------------------------------------------
// fp16 GEMM via mma.sync: C[M,N] = A[M,K] @ B[N,K]^T
// EPI: 1 = fp16 store (*scale), 2 = fp32 + bias store.
// 128x128 CTA tile, 8 warps (2m x 4n), K-chunk 32, 2-stage cp.async.
// ---------------------------------------------------------------------------
#define GROWB    80                       // smem row stride bytes (40 halves)
#define GA_BYTES (128*GROWB)              // 10240 B per array tile
#define GSTG     (2*GA_BYTES)             // A + B per stage
#define GSMEM    (2*GSTG)                 // 40960 B

template<int EPI>
__global__ __launch_bounds__(256, 2) void gemm_fp16(
    const __half* __restrict__ A, const __half* __restrict__ Bm,
    float* __restrict__ Cf, const float* __restrict__ bias,
    __half* __restrict__ Ch, float scale, int Nn, int Kk)
{
    extern __shared__ char smem[];
    const uint32_t sb = smem_u32(smem);
    const int tid = threadIdx.x, lane = tid & 31, wid = tid >> 5;
    const int wm = wid >> 2, wn = wid & 3;
    const int g = lane >> 2, q = lane & 3;
    const int m0 = blockIdx.y * 128, n0 = blockIdx.x * 128;

    const __half* gsrc[2] = { A + (size_t)m0 * Kk, Bm + (size_t)n0 * Kk };
    const int larr = tid & 1, tg = tid >> 1;
    const __half* lsrc = gsrc[larr];

    auto load_chunk = [&](int c, int st) {
        uint32_t sdst = sb + st * GSTG + larr * GA_BYTES;
        int k0 = c * 32;
        #pragma unroll
        for (int i = 0; i < 4; i++) {
            int e = tg + i * 128;            // 0..511
            int row = e >> 2, cg = e & 3;
            cpa16(sdst + row * GROWB + cg * 16,
                  lsrc + (size_t)row * Kk + k0 + cg * 8);
        }
    };

    float acc[4][4][4];
    #pragma unroll
    for (int a = 0; a < 4; a++)
        #pragma unroll
        for (int b = 0; b < 4; b++)
            #pragma unroll
            for (int d = 0; d < 4; d++) acc[a][b][d] = 0.f;

    load_chunk(0, 0); CP_COMMIT();
    load_chunk(1, 1); CP_COMMIT();

    const int NC = Kk / 32;
    const int arow = wm * 64 + (lane & 15);
    const int acolh = (lane >> 4) << 3;
    const int jj = lane >> 3, rin = lane & 7;

    for (int c = 0; c < NC; c++) {
        int st = c & 1;
        CP_WAIT1();
        __syncthreads();
        uint32_t sA = sb + st * GSTG;
        uint32_t sB = sA + GA_BYTES;

        #pragma unroll
        for (int ks = 0; ks < 2; ks++) {
            uint32_t af[4][4];
            int acol = ks * 16 + acolh;
            #pragma unroll
            for (int mt = 0; mt < 4; mt++)
                ldsm4(af[mt], sA + (arow + mt * 16) * GROWB + acol * 2);
            #pragma unroll
            for (int nt2 = 0; nt2 < 2; nt2++) {
                int brow = wn * 32 + nt2 * 16 + ((jj >> 1) << 3) + rin;
                int bcol = ks * 16 + ((jj & 1) << 3);
                uint32_t bf[4];
                ldsm4(bf, sB + brow * GROWB + bcol * 2);
                #pragma unroll
                for (int mt = 0; mt < 4; mt++)
                    #pragma unroll
                    for (int hf = 0; hf < 2; hf++)
                        mma_f16(acc[mt][nt2 * 2 + hf], af[mt],
                                bf[hf*2], bf[hf*2+1]);
            }
        }
        __syncthreads();
        if (c + 2 < NC) load_chunk(c + 2, st);
        CP_COMMIT();
    }

    #pragma unroll
    for (int mt = 0; mt < 4; mt++)
        #pragma unroll
        for (int nt = 0; nt < 4; nt++) {
            int r   = m0 + wm * 64 + mt * 16 + g;
            int col = n0 + wn * 32 + nt * 8 + 2 * q;
            float v0 = acc[mt][nt][0] * scale, v1 = acc[mt][nt][1] * scale;
            float v2 = acc[mt][nt][2] * scale, v3 = acc[mt][nt][3] * scale;
            if (EPI == 2) {
                float2 bb = *(const float2*)(bias + col);
                *(float2*)(Cf + (size_t)r * Nn + col) =
                    make_float2(v0 + bb.x, v1 + bb.y);
                *(float2*)(Cf + (size_t)(r + 8) * Nn + col) =
                    make_float2(v2 + bb.x, v3 + bb.y);
            } else {
                *(__half2*)(Ch + (size_t)r * Nn + col) =
                    __floats2half2_rn(v0, v1);
                *(__half2*)(Ch + (size_t)(r + 8) * Nn + col) =
                    __floats2half2_rn(v2, v3);
            }
        }
}

// ---------------------------------------------------------------------------
// Flash attention, all fp16 single-term. CTA: 128 q-rows, 8 warps (m16 each).
// KV tiles of 32 keys, 2-stage cp.async. Q fragments hoisted to registers.
// ---------------------------------------------------------------------------
#define DPAD_B  336                       // smem row stride bytes (168 halves)
#define QBYTES  (128*DPAD_B)              // 43008
#define KVARR   (32*DPAD_B)               // 10752
#define KVSTAGE (2*KVARR)                 // Kf, Vf = 21504
#define FSMEM   (QBYTES + 2*KVSTAGE)      // 86016

__global__ __launch_bounds__(256, 1) void flash_fp16(
    const __half* __restrict__ qf, const __half* __restrict__ kf,
    const __half* __restrict__ vf, __half* __restrict__ of)
{
    extern __shared__ char smem[];
    const uint32_t sb = smem_u32(smem);
    const int tid = threadIdx.x, lane = tid & 31, wid = tid >> 5;
    const int g = lane >> 2, q = lane & 3;
    const int qt = blockIdx.x, h = blockIdx.y, b = blockIdx.z;
    const size_t rowbase = (size_t)b * S_ + qt * 128;
    const int hcol = h * D_;

    {   // Q tile (128 x 160 fp16)
        #pragma unroll
        for (int i = 0; i < 10; i++) {
            int e = tid + i * 256;            // 0..2559
            int row = e / 20, cg = e % 20;
            cpa16(sb + row * DPAD_B + cg * 16,
                  qf + (rowbase + row) * C_ + hcol + cg * 8);
        }
    }
    const __half* kvsrc[2] = { kf, vf };
    const int karr = tid & 1, ktg = tid >> 1;
    const __half* ksrc = kvsrc[karr];
    auto load_kv = [&](int t, int st) {
        uint32_t dst = sb + QBYTES + st * KVSTAGE + karr * KVARR;
        size_t krow0 = (size_t)b * S_ + t * 32;
        #pragma unroll
        for (int i = 0; i < 5; i++) {
            int e = ktg + i * 128;            // 0..639
            int row = e / 20, cg = e % 20;
            cpa16(dst + row * DPAD_B + cg * 16,
                  ksrc + (krow0 + row) * C_ + hcol + cg * 8);
        }
    };
    load_kv(0, 0); CP_COMMIT();               // group0: Q + KV tile 0
    load_kv(1, 1); CP_COMMIT();               // group1: KV tile 1

    const int arow = wid * 16 + (lane & 15);
    const int acolh = (lane >> 4) << 3;
    const int jj = lane >> 3, rin = lane & 7;

    // hoist Q fragments (group0 complete after this wait)
    CP_WAIT1();
    __syncthreads();
    uint32_t qfr[10][4];
    #pragma unroll
    for (int ks = 0; ks < 10; ks++)
        ldsm4(qfr[ks], sb + arow * DPAD_B + (ks * 16 + acolh) * 2);

    float o[20][4];
    #pragma unroll
    for (int d = 0; d < 20; d++)
        #pragma unroll
        for (int i = 0; i < 4; i++) o[d][i] = 0.f;
    float m0r = -INFINITY, m1r = -INFINITY, l0r = 0.f, l1r = 0.f;

    for (int t = 0; t < S_ / 32; t++) {
        int st = t & 1;
        CP_WAIT1();
        __syncthreads();
        uint32_t sK = sb + QBYTES + st * KVSTAGE;
        uint32_t sV = sK + KVARR;

        // ---- S = Q K^T (fp16 single) ----
        float sacc[4][4];
        #pragma unroll
        for (int nt = 0; nt < 4; nt++)
            #pragma unroll
            for (int i = 0; i < 4; i++) sacc[nt][i] = 0.f;

        #pragma unroll
        for (int ks = 0; ks < 10; ks++) {
            #pragma unroll
            for (int nt2 = 0; nt2 < 2; nt2++) {
                int brow = nt2 * 16 + ((jj >> 1) << 3) + rin;
                int bcol = ks * 16 + ((jj & 1) << 3);
                uint32_t bf[4];
                ldsm4(bf, sK + brow * DPAD_B + bcol * 2);
                #pragma unroll
                for (int hf = 0; hf < 2; hf++)
                    mma_f16(sacc[nt2 * 2 + hf], qfr[ks],
                            bf[hf*2], bf[hf*2+1]);
            }
        }

        // ---- online softmax ----
        float mx0 = -INFINITY, mx1 = -INFINITY;
        #pragma unroll
        for (int nt = 0; nt < 4; nt++) {
            mx0 = fmaxf(mx0, fmaxf(sacc[nt][0], sacc[nt][1]));
            mx1 = fmaxf(mx1, fmaxf(sacc[nt][2], sacc[nt][3]));
        }
        mx0 = fmaxf(mx0, __shfl_xor_sync(0xffffffffu, mx0, 1));
        mx0 = fmaxf(mx0, __shfl_xor_sync(0xffffffffu, mx0, 2));
        mx1 = fmaxf(mx1, __shfl_xor_sync(0xffffffffu, mx1, 1));
        mx1 = fmaxf(mx1, __shfl_xor_sync(0xffffffffu, mx1, 2));
        float mn0 = fmaxf(m0r, mx0), mn1 = fmaxf(m1r, mx1);
        float alpha0 = __expf(m0r - mn0), alpha1 = __expf(m1r - mn1);
        m0r = mn0; m1r = mn1;

        float s0 = 0.f, s1 = 0.f;
        #pragma unroll
        for (int nt = 0; nt < 4; nt++) {
            sacc[nt][0] = __expf(sacc[nt][0] - mn0); s0 += sacc[nt][0];
            sacc[nt][1] = __expf(sacc[nt][1] - mn0); s0 += sacc[nt][1];
            sacc[nt][2] = __expf(sacc[nt][2] - mn1); s1 += sacc[nt][2];
            sacc[nt][3] = __expf(sacc[nt][3] - mn1); s1 += sacc[nt][3];
        }
        s0 += __shfl_xor_sync(0xffffffffu, s0, 1);
        s0 += __shfl_xor_sync(0xffffffffu, s0, 2);
        s1 += __shfl_xor_sync(0xffffffffu, s1, 1);
        s1 += __shfl_xor_sync(0xffffffffu, s1, 2);
        l0r = l0r * alpha0 + s0;
        l1r = l1r * alpha1 + s1;

        #pragma unroll
        for (int d = 0; d < 20; d++) {
            o[d][0] *= alpha0; o[d][1] *= alpha0;
            o[d][2] *= alpha1; o[d][3] *= alpha1;
        }

        // ---- O += P V (fp16 single) ----
        #pragma unroll
        for (int kt = 0; kt < 2; kt++) {
            uint32_t pF[4];
            pF[0] = pack_h2(sacc[2*kt  ][0], sacc[2*kt  ][1]);
            pF[1] = pack_h2(sacc[2*kt  ][2], sacc[2*kt  ][3]);
            pF[2] = pack_h2(sacc[2*kt+1][0], sacc[2*kt+1][1]);
            pF[3] = pack_h2(sacc[2*kt+1][2], sacc[2*kt+1][3]);
            int vk = kt * 16 + ((jj & 1) << 3) + rin;
            #pragma unroll
            for (int np = 0; np < 10; np++) {
                int vd = np * 16 + ((jj >> 1) << 3);
                uint32_t vfr[4];
                ldsm4t(vfr, sV + vk * DPAD_B + vd * 2);
                #pragma unroll
                for (int hf = 0; hf < 2; hf++)
                    mma_f16(o[np * 2 + hf], pF, vfr[hf*2], vfr[hf*2+1]);
            }
        }
        __syncthreads();
        if (t + 2 < S_ / 32) load_kv(t + 2, st);
        CP_COMMIT();
    }

    // ---- epilogue: normalize, store fp16 ----
    float i0 = 1.f / l0r, i1 = 1.f / l1r;
    size_t r0 = rowbase + wid * 16 + g, r1 = r0 + 8;
    #pragma unroll
    for (int nt = 0; nt < 20; nt++) {
        int col = hcol + nt * 8 + 2 * q;
        *(__half2*)(of + r0 * C_ + col) =
            __floats2half2_rn(o[nt][0] * i0, o[nt][1] * i0);
        *(__half2*)(of + r1 * C_ + col) =
            __floats2half2_rn(o[nt][2] * i1, o[nt][3] * i1);
    }
}

// ---------------------------------------------------------------------------
extern "C" void kernel_launch(void* const* d_in, const int* in_sizes, int n_in,
                              void* d_out, int out_size)
{
    const float* hs = (const float*)d_in[0];
    const float* wq = (const float*)d_in[1];
    const float* wk = (const float*)d_in[2];
    const float* wv = (const float*)d_in[3];
    const float* wo = (const float*)d_in[4];
    const float* bo = (const float*)d_in[5];
    float* out = (float*)d_out;

    __half *hF, *qfp, *kfp, *vfp, *ofp, *wqf, *wkf, *wvf, *wof;
    cudaGetSymbolAddress((void**)&hF,  g_hF);
    cudaGetSymbolAddress((void**)&qfp, g_qf);
    cudaGetSymbolAddress((void**)&kfp, g_kf);
    cudaGetSymbolAddress((void**)&vfp, g_vf);
    cudaGetSymbolAddress((void**)&ofp, g_of);
    cudaGetSymbolAddress((void**)&wqf, g_wqf);
    cudaGetSymbolAddress((void**)&wkf, g_wkf);
    cudaGetSymbolAddress((void**)&wvf, g_wvf);
    cudaGetSymbolAddress((void**)&wof, g_wof);

    const size_t nA = (size_t)M_ * C_;
    convert_half_kernel<<<(int)((nA + 255) / 256), 256>>>(hs, hF, nA);
    dim3 tb(32, 8), tg4(C_ / 32, C_ / 32, 4);
    transpose_half4_kernel<<<tg4, tb>>>(wq, wk, wv, wo,
                                        wqf, wkf, wvf, wof, C_, C_);

    cudaFuncSetAttribute(gemm_fp16<1>,
                         cudaFuncAttributeMaxDynamicSharedMemorySize, GSMEM);
    cudaFuncSetAttribute(gemm_fp16<2>,
                         cudaFuncAttributeMaxDynamicSharedMemorySize, GSMEM);
    cudaFuncSetAttribute(flash_fp16,
                         cudaFuncAttributeMaxDynamicSharedMemorySize, FSMEM);

    const float qscale = 0.07905694150420949f;   // 1/sqrt(160)
    dim3 gg(C_ / 128, M_ / 128);
    gemm_fp16<1><<<gg, 256, GSMEM>>>(hF, wqf, nullptr, nullptr, qfp,
                                     qscale, C_, C_);
    gemm_fp16<1><<<gg, 256, GSMEM>>>(hF, wkf, nullptr, nullptr, kfp,
                                     1.f, C_, C_);
    gemm_fp16<1><<<gg, 256, GSMEM>>>(hF, wvf, nullptr, nullptr, vfp,
                                     1.f, C_, C_);

    flash_fp16<<<dim3(S_ / 128, H_, B_), 256, FSMEM>>>(qfp, kfp, vfp, ofp);

    gemm_fp16<2><<<gg, 256, GSMEM>>>(ofp, wof, out, bo, nullptr,
                                     1.f, C_, C_);
}